// round 3
// baseline (speedup 1.0000x reference)
#include <cuda_runtime.h>
#include <math.h>

#define D_MODEL 1024
#define D_STATE 16
#define D_CONV  4
#define D_INNER 2048
#define DT_RANK 64
#define N_LAYERS 4
#define BATCH 2
#define SEQ 1024
#define NROWS (BATCH*SEQ)            // 2048
#define XDBL_W (DT_RANK + 2*D_STATE) // 96
#define LN_EPS 1e-5f

// ---------------- scratch (device globals; no allocations allowed) ----------
__device__ float g_x   [NROWS * D_MODEL];        // residual stream
__device__ float g_ln  [NROWS * D_MODEL];        // layernorm output
__device__ float g_xz  [NROWS * 2 * D_INNER];    // in_proj output (xm_pre | z)
__device__ float g_xm  [NROWS * D_INNER];        // conv + silu output
__device__ float g_xdbl[NROWS * XDBL_W];         // x_proj output (dt_lowrank|B|C)
__device__ float g_dt  [NROWS * D_INNER];        // softplus(dt)
__device__ float g_y   [NROWS * D_INNER];        // scan output * silu(z)

// ---------------- helpers ---------------------------------------------------
__device__ __forceinline__ float siluf(float v) { return v / (1.f + __expf(-v)); }
__device__ __forceinline__ float softplusf(float v) {
    return v > 20.f ? v : log1pf(__expf(v));
}

// ---------------- copy ------------------------------------------------------
__global__ void copy4_kernel(const float* __restrict__ src, float* __restrict__ dst, int n4) {
    int i = blockIdx.x * blockDim.x + threadIdx.x;
    if (i < n4) reinterpret_cast<float4*>(dst)[i] = reinterpret_cast<const float4*>(src)[i];
}

// ---------------- layernorm (one block per row, D=1024) ---------------------
__global__ void layernorm_kernel(const float* __restrict__ src, float* __restrict__ dst,
                                 const float* __restrict__ g, const float* __restrict__ b) {
    int row = blockIdx.x;
    int t = threadIdx.x;                      // 256 threads
    const float4* s4 = reinterpret_cast<const float4*>(src + (size_t)row * D_MODEL);
    float4 v = s4[t];
    float sum = v.x + v.y + v.z + v.w;
    float sq  = v.x*v.x + v.y*v.y + v.z*v.z + v.w*v.w;
    #pragma unroll
    for (int o = 16; o; o >>= 1) {
        sum += __shfl_xor_sync(0xffffffffu, sum, o);
        sq  += __shfl_xor_sync(0xffffffffu, sq,  o);
    }
    __shared__ float ssum[8], ssq[8];
    int lane = t & 31, wid = t >> 5;
    if (lane == 0) { ssum[wid] = sum; ssq[wid] = sq; }
    __syncthreads();
    float ts = 0.f, tq = 0.f;
    #pragma unroll
    for (int i = 0; i < 8; i++) { ts += ssum[i]; tq += ssq[i]; }
    float mu = ts * (1.f / D_MODEL);
    float var = tq * (1.f / D_MODEL) - mu * mu;
    float rs = rsqrtf(var + LN_EPS);
    float4 gv = reinterpret_cast<const float4*>(g)[t];
    float4 bv = reinterpret_cast<const float4*>(b)[t];
    float4 o;
    o.x = (v.x - mu) * rs * gv.x + bv.x;
    o.y = (v.y - mu) * rs * gv.y + bv.y;
    o.z = (v.z - mu) * rs * gv.z + bv.z;
    o.w = (v.w - mu) * rs * gv.w + bv.w;
    reinterpret_cast<float4*>(dst + (size_t)row * D_MODEL)[t] = o;
}

// ---------------- SGEMM: C[M,N] = A[M,K] @ B[N,K]^T -------------------------
// BM=BN=128, BK=8, TM=TN=8, 256 threads.
// 2-stage pipeline: register prefetch of next global tile + double-buffered
// smem (one __syncthreads per k-tile).
// EPI: 0 = plain store, 1 = softplus(acc + bias[n]), 2 = C += acc (residual)
template<int EPI>
__global__ void __launch_bounds__(256, 2)
sgemm128(const float* __restrict__ A, int lda,
         const float* __restrict__ B, int ldb,
         float* __restrict__ C, int ldc,
         int N, int K, const float* __restrict__ bias) {
    __shared__ float As[2][8][128];
    __shared__ float Bs[2][8][128];
    int tid = threadIdx.x;
    int tx = tid & 15, ty = tid >> 4;
    int aRow = tid >> 1, aK = (tid & 1) << 2;

    const float* Ab = A + (size_t)(blockIdx.y * 128 + aRow) * lda + aK;
    int bn = blockIdx.x * 128 + aRow;
    const float* Bb = B + (size_t)bn * ldb + aK;
    bool bvalid = bn < N;

    float acc[8][8];
    #pragma unroll
    for (int i = 0; i < 8; i++)
        #pragma unroll
        for (int j = 0; j < 8; j++) acc[i][j] = 0.f;

    int ktiles = K >> 3;

    // prefetch tile 0 -> regs -> smem buf 0
    float4 av = *reinterpret_cast<const float4*>(Ab);
    float4 bv = bvalid ? *reinterpret_cast<const float4*>(Bb)
                       : make_float4(0.f, 0.f, 0.f, 0.f);
    As[0][aK+0][aRow] = av.x; As[0][aK+1][aRow] = av.y;
    As[0][aK+2][aRow] = av.z; As[0][aK+3][aRow] = av.w;
    Bs[0][aK+0][aRow] = bv.x; Bs[0][aK+1][aRow] = bv.y;
    Bs[0][aK+2][aRow] = bv.z; Bs[0][aK+3][aRow] = bv.w;
    __syncthreads();

    for (int kt = 0; kt < ktiles; kt++) {
        int cur = kt & 1, nxt = cur ^ 1;
        // issue next tile's global loads early
        if (kt + 1 < ktiles) {
            av = *reinterpret_cast<const float4*>(Ab + (kt + 1) * 8);
            bv = bvalid ? *reinterpret_cast<const float4*>(Bb + (kt + 1) * 8)
                        : make_float4(0.f, 0.f, 0.f, 0.f);
        }
        // compute from current buffer
        #pragma unroll
        for (int k = 0; k < 8; k++) {
            float4 m0 = *reinterpret_cast<const float4*>(&As[cur][k][ty*8]);
            float4 m1 = *reinterpret_cast<const float4*>(&As[cur][k][ty*8+4]);
            float4 n0 = *reinterpret_cast<const float4*>(&Bs[cur][k][tx*8]);
            float4 n1 = *reinterpret_cast<const float4*>(&Bs[cur][k][tx*8+4]);
            float rm[8] = {m0.x,m0.y,m0.z,m0.w,m1.x,m1.y,m1.z,m1.w};
            float rn[8] = {n0.x,n0.y,n0.z,n0.w,n1.x,n1.y,n1.z,n1.w};
            #pragma unroll
            for (int i = 0; i < 8; i++)
                #pragma unroll
                for (int j = 0; j < 8; j++)
                    acc[i][j] = fmaf(rm[i], rn[j], acc[i][j]);
        }
        // store next tile into the other buffer, then one barrier
        if (kt + 1 < ktiles) {
            As[nxt][aK+0][aRow] = av.x; As[nxt][aK+1][aRow] = av.y;
            As[nxt][aK+2][aRow] = av.z; As[nxt][aK+3][aRow] = av.w;
            Bs[nxt][aK+0][aRow] = bv.x; Bs[nxt][aK+1][aRow] = bv.y;
            Bs[nxt][aK+2][aRow] = bv.z; Bs[nxt][aK+3][aRow] = bv.w;
            __syncthreads();
        }
    }

    #pragma unroll
    for (int i = 0; i < 8; i++) {
        int m = blockIdx.y * 128 + ty * 8 + i;
        #pragma unroll
        for (int j = 0; j < 8; j++) {
            int n = blockIdx.x * 128 + tx * 8 + j;
            if (n < N) {
                float v = acc[i][j];
                if (EPI == 1) v = softplusf(v + bias[n]);
                else if (EPI == 2) v += C[(size_t)m * ldc + n];
                C[(size_t)m * ldc + n] = v;
            }
        }
    }
}

// ---------------- depthwise causal conv (D_CONV=4) + bias + silu ------------
// xz first half [*, 0:2048] is the conv input (row stride 2*D_INNER).
__global__ void conv_silu_kernel(const float* __restrict__ xz,
                                 const float* __restrict__ cw,
                                 const float* __restrict__ cb,
                                 float* __restrict__ xm) {
    int d = blockIdx.x * blockDim.x + threadIdx.x;  // 0..2047
    int l = blockIdx.y;                             // 0..1023
    int b = blockIdx.z;                             // 0..1
    float w0 = cw[d*4+0], w1 = cw[d*4+1], w2 = cw[d*4+2], w3 = cw[d*4+3];
    const float* base = xz + (size_t)b * SEQ * (2*D_INNER) + d;
    float acc = cb[d];
    if (l >= 3) acc = fmaf(base[(size_t)(l-3)*(2*D_INNER)], w0, acc);
    if (l >= 2) acc = fmaf(base[(size_t)(l-2)*(2*D_INNER)], w1, acc);
    if (l >= 1) acc = fmaf(base[(size_t)(l-1)*(2*D_INNER)], w2, acc);
    acc = fmaf(base[(size_t)l*(2*D_INNER)], w3, acc);
    xm[((size_t)(b*SEQ) + l) * D_INNER + d] = siluf(acc);
}

// ---------------- selective scan --------------------------------------------
// 16 lanes per channel (one per state). warp = 2 channels. Fused epilogue:
// y = (sum_s h*C + xm*D) * silu(z)
__global__ void scan_kernel(const float* __restrict__ dt,
                            const float* __restrict__ xm,
                            const float* __restrict__ xdbl,
                            const float* __restrict__ xz,
                            const float* __restrict__ A_log,
                            const float* __restrict__ Dskip,
                            float* __restrict__ y) {
    int t = blockIdx.x * blockDim.x + threadIdx.x;   // 65536 threads
    int s = t & 15;
    int ch = t >> 4;                                  // 0..4095
    int b = ch >> 11;
    int d = ch & (D_INNER - 1);

    float A  = -__expf(A_log[d * D_STATE + s]);
    float Dv = Dskip[d];
    float h = 0.f;

    const float* dt_p = dt   + (size_t)b * SEQ * D_INNER + d;
    const float* xm_p = xm   + (size_t)b * SEQ * D_INNER + d;
    const float* bc_p = xdbl + (size_t)b * SEQ * XDBL_W;
    const float* z_p  = xz   + (size_t)b * SEQ * (2*D_INNER) + D_INNER + d;
    float*       y_p  = y    + (size_t)b * SEQ * D_INNER + d;

    for (int l = 0; l < SEQ; l++) {
        float dtv = dt_p[(size_t)l * D_INNER];
        float xv  = xm_p[(size_t)l * D_INNER];
        float Bv  = bc_p[(size_t)l * XDBL_W + DT_RANK + s];
        float Cv  = bc_p[(size_t)l * XDBL_W + DT_RANK + D_STATE + s];
        float dA  = __expf(dtv * A);
        h = fmaf(h, dA, dtv * Bv * xv);
        float p = h * Cv;
        p += __shfl_xor_sync(0xffffffffu, p, 8);
        p += __shfl_xor_sync(0xffffffffu, p, 4);
        p += __shfl_xor_sync(0xffffffffu, p, 2);
        p += __shfl_xor_sync(0xffffffffu, p, 1);
        if (s == 0) {
            float zv = z_p[(size_t)l * (2*D_INNER)];
            y_p[(size_t)l * D_INNER] = (p + xv * Dv) * siluf(zv);
        }
    }
}

// ---------------- launcher --------------------------------------------------
extern "C" void kernel_launch(void* const* d_in, const int* in_sizes, int n_in,
                              void* d_out, int out_size) {
    const float* x      = (const float*)d_in[0];
    const float* in_w   = (const float*)d_in[1];
    const float* conv_w = (const float*)d_in[2];
    const float* conv_b = (const float*)d_in[3];
    const float* xp_w   = (const float*)d_in[4];
    const float* dt_w   = (const float*)d_in[5];
    const float* dt_b   = (const float*)d_in[6];
    const float* A_log  = (const float*)d_in[7];
    const float* Dskip  = (const float*)d_in[8];
    const float* out_w  = (const float*)d_in[9];
    const float* ln_g   = (const float*)d_in[10];
    const float* ln_b   = (const float*)d_in[11];

    float *gx, *gln, *gxz, *gxm, *gxdbl, *gdt, *gy;
    cudaGetSymbolAddress((void**)&gx,    g_x);
    cudaGetSymbolAddress((void**)&gln,   g_ln);
    cudaGetSymbolAddress((void**)&gxz,   g_xz);
    cudaGetSymbolAddress((void**)&gxm,   g_xm);
    cudaGetSymbolAddress((void**)&gxdbl, g_xdbl);
    cudaGetSymbolAddress((void**)&gdt,   g_dt);
    cudaGetSymbolAddress((void**)&gy,    g_y);

    // residual stream init
    {
        int n4 = NROWS * D_MODEL / 4;
        copy4_kernel<<<(n4 + 255) / 256, 256>>>(x, gx, n4);
    }

    for (int i = 0; i < N_LAYERS; i++) {
        const float* inw_i = in_w  + (size_t)i * (2*D_INNER) * D_MODEL;
        const float* cw_i  = conv_w + (size_t)i * D_INNER * D_CONV;
        const float* cb_i  = conv_b + (size_t)i * D_INNER;
        const float* xpw_i = xp_w  + (size_t)i * XDBL_W * D_INNER;
        const float* dtw_i = dt_w  + (size_t)i * D_INNER * DT_RANK;
        const float* dtb_i = dt_b  + (size_t)i * D_INNER;
        const float* Al_i  = A_log + (size_t)i * D_INNER * D_STATE;
        const float* Ds_i  = Dskip + (size_t)i * D_INNER;
        const float* ow_i  = out_w + (size_t)i * D_MODEL * D_INNER;

        // 1. layernorm
        layernorm_kernel<<<NROWS, 256>>>(gx, gln, ln_g, ln_b);
        // 2. in_proj: xz[2048,4096] = ln @ in_w^T
        sgemm128<0><<<dim3(2*D_INNER/128, NROWS/128), 256>>>(
            gln, D_MODEL, inw_i, D_MODEL, gxz, 2*D_INNER, 2*D_INNER, D_MODEL, nullptr);
        // 3. causal depthwise conv + bias + silu -> xm
        conv_silu_kernel<<<dim3(D_INNER/256, SEQ, BATCH), 256>>>(gxz, cw_i, cb_i, gxm);
        // 4. x_proj: xdbl[2048,96] = xm @ xp_w^T
        sgemm128<0><<<dim3(1, NROWS/128), 256>>>(
            gxm, D_INNER, xpw_i, D_INNER, gxdbl, XDBL_W, XDBL_W, D_INNER, nullptr);
        // 5. dt: softplus(xdbl[:, :64] @ dt_w^T + dt_b)
        sgemm128<1><<<dim3(D_INNER/128, NROWS/128), 256>>>(
            gxdbl, XDBL_W, dtw_i, DT_RANK, gdt, D_INNER, D_INNER, DT_RANK, dtb_i);
        // 6. selective scan + gating -> y
        scan_kernel<<<(BATCH*D_INNER*D_STATE)/256, 256>>>(
            gdt, gxm, gxdbl, gxz, Al_i, Ds_i, gy);
        // 7. out_proj with fused residual: x += y @ out_w^T
        sgemm128<2><<<dim3(D_MODEL/128, NROWS/128), 256>>>(
            gy, D_INNER, ow_i, D_INNER, gx, D_MODEL, D_MODEL, D_INNER, nullptr);
    }

    // final layernorm -> output
    layernorm_kernel<<<NROWS, 256>>>(gx, (float*)d_out, ln_g, ln_b);
}

// round 6
// speedup vs baseline: 1.3839x; 1.3839x over previous
#include <cuda_runtime.h>
#include <cuda_bf16.h>
#include <math.h>
#include <cstdint>

#define D_MODEL 1024
#define D_STATE 16
#define D_CONV  4
#define D_INNER 2048
#define DT_RANK 64
#define N_LAYERS 4
#define BATCH 2
#define SEQ 1024
#define NROWS (BATCH*SEQ)            // 2048
#define XDBL_W (DT_RANK + 2*D_STATE) // 96
#define LN_EPS 1e-5f

// ---------------- scratch (device globals; no allocations allowed) ----------
__device__ float g_x   [NROWS * D_MODEL];
__device__ float g_ln  [NROWS * D_MODEL];
__device__ float g_xz  [NROWS * 2 * D_INNER];
__device__ float g_xm  [NROWS * D_INNER];
__device__ float g_xdbl[NROWS * XDBL_W];
__device__ float g_dt  [NROWS * D_INNER];
__device__ float g_y   [NROWS * D_INNER];
// bf16-split operands: A3 up to [2048 x 6144], B3 up to [4096 x 3072]
__device__ __nv_bfloat16 g_a3[NROWS * 3 * D_INNER];
__device__ __nv_bfloat16 g_b3[2 * D_INNER * 3 * D_MODEL];

// ---------------- helpers ---------------------------------------------------
__device__ __forceinline__ float siluf(float v) { return v / (1.f + __expf(-v)); }
__device__ __forceinline__ float softplusf(float v) {
    return v > 20.f ? v : log1pf(__expf(v));
}
__device__ __forceinline__ uint32_t smem_to_u32(const void* p) {
    uint32_t a;
    asm("{ .reg .u64 t; cvta.to.shared.u64 t, %1; cvt.u32.u64 %0, t; }" : "=r"(a) : "l"(p));
    return a;
}
__device__ __forceinline__ void cp_async16(uint32_t saddr, const void* gaddr) {
    asm volatile("cp.async.cg.shared.global [%0], [%1], 16;" :: "r"(saddr), "l"(gaddr));
}
__device__ __forceinline__ void cp_commit() {
    asm volatile("cp.async.commit_group;" ::: "memory");
}
__device__ __forceinline__ void ldsm_x4(uint32_t (&r)[4], uint32_t addr) {
    asm volatile("ldmatrix.sync.aligned.m8n8.x4.shared.b16 {%0,%1,%2,%3}, [%4];"
                 : "=r"(r[0]), "=r"(r[1]), "=r"(r[2]), "=r"(r[3]) : "r"(addr));
}
__device__ __forceinline__ void mma16816(float* c, const uint32_t* a, uint32_t b0, uint32_t b1) {
    asm volatile(
        "mma.sync.aligned.m16n8k16.row.col.f32.bf16.bf16.f32 "
        "{%0,%1,%2,%3}, {%4,%5,%6,%7}, {%8,%9}, {%0,%1,%2,%3};"
        : "+f"(c[0]), "+f"(c[1]), "+f"(c[2]), "+f"(c[3])
        : "r"(a[0]), "r"(a[1]), "r"(a[2]), "r"(a[3]), "r"(b0), "r"(b1));
}

// ---------------- fp32 -> bf16 hi/lo split conversion -----------------------
// WT=0 (activation): dst row = [hi | lo | hi]
// WT=1 (weight):     dst row = [hi | hi | lo]
// rows >= Rvalid are zero (padding). grid*block == Rpad*K exactly.
template<int WT>
__global__ void convert_split(const float* __restrict__ src, int lda, int Rvalid, int K,
                              __nv_bfloat16* __restrict__ dst) {
    int idx = blockIdx.x * blockDim.x + threadIdx.x;
    int r = idx / K, k = idx - r * K;
    __nv_bfloat16 hi = __float2bfloat16(0.f), lo = hi;
    if (r < Rvalid) {
        float v = src[(size_t)r * lda + k];
        hi = __float2bfloat16(v);
        lo = __float2bfloat16(v - __bfloat162float(hi));
    }
    size_t base = (size_t)r * 3 * K;
    if (WT) {
        dst[base + k] = hi; dst[base + K + k] = hi; dst[base + 2*K + k] = lo;
    } else {
        dst[base + k] = hi; dst[base + K + k] = lo; dst[base + 2*K + k] = hi;
    }
}

// ---------------- HMMA GEMM: C[M,N] = A3[M,K3] @ B3[N,K3]^T ------------------
// CTA tile 128x128, BK=32, 256 threads (8 warps, 2x4), warp tile 64x32.
// mma.sync m16n8k16 bf16 -> fp32 regs. cp.async double-buffered smem,
// +8 bf16 row pad (80B stride) => conflict-free ldmatrix.
// EPI: 0 plain, 1 softplus(acc+bias[n]), 2 C += acc
#define ROWB 80          // padded row stride in bytes (40 bf16)
#define ABUF_BYTES 10240 // 128*80
#define TILE_BYTES 20480 // A+B
template<int EPI>
__global__ void __launch_bounds__(256, 2)
mma_gemm(const __nv_bfloat16* __restrict__ A3, const __nv_bfloat16* __restrict__ B3,
         float* __restrict__ C, int ldc, int N, int K3, const float* __restrict__ bias) {
    __shared__ __align__(128) unsigned char sm[2 * TILE_BYTES];
    uint32_t smbase = smem_to_u32(sm);

    int tid = threadIdx.x;
    int wid = tid >> 5, lid = tid & 31;
    int warp_m = wid >> 2;           // 0..1 -> m offset *64
    int warp_n = wid & 3;            // 0..3 -> n offset *32
    int q = lid >> 3, r8 = lid & 7;  // ldmatrix lane decomposition

    const __nv_bfloat16* Abase = A3 + (size_t)(blockIdx.y * 128) * K3;
    const __nv_bfloat16* Bbase = B3 + (size_t)(blockIdx.x * 128) * K3;

    int ldrow = tid >> 2, ldj = tid & 3;   // this thread's load slots (row, 16B chunk)

    float acc[4][4][4];
    #pragma unroll
    for (int i = 0; i < 4; i++)
        #pragma unroll
        for (int j = 0; j < 4; j++)
            #pragma unroll
            for (int v = 0; v < 4; v++) acc[i][j][v] = 0.f;

    int ktiles = K3 >> 5;   // BK=32

    // prologue: tile 0 -> buffer 0
    {
        uint32_t sa = smbase + (uint32_t)(ldrow * ROWB + ldj * 16);
        cp_async16(sa,               Abase + (size_t)ldrow * K3 + ldj * 8);
        cp_async16(sa + ABUF_BYTES,  Bbase + (size_t)ldrow * K3 + ldj * 8);
        sa += 64 * ROWB;
        cp_async16(sa,               Abase + (size_t)(ldrow + 64) * K3 + ldj * 8);
        cp_async16(sa + ABUF_BYTES,  Bbase + (size_t)(ldrow + 64) * K3 + ldj * 8);
        cp_commit();
    }

    for (int c = 0; c < ktiles; c++) {
        if (c + 1 < ktiles) {
            uint32_t sa = smbase + (uint32_t)(((c + 1) & 1) * TILE_BYTES + ldrow * ROWB + ldj * 16);
            int kk = (c + 1) * 32;
            cp_async16(sa,               Abase + (size_t)ldrow * K3 + kk + ldj * 8);
            cp_async16(sa + ABUF_BYTES,  Bbase + (size_t)ldrow * K3 + kk + ldj * 8);
            sa += 64 * ROWB;
            cp_async16(sa,               Abase + (size_t)(ldrow + 64) * K3 + kk + ldj * 8);
            cp_async16(sa + ABUF_BYTES,  Bbase + (size_t)(ldrow + 64) * K3 + kk + ldj * 8);
            cp_commit();
            asm volatile("cp.async.wait_group 1;" ::: "memory");
        } else {
            asm volatile("cp.async.wait_group 0;" ::: "memory");
        }
        __syncthreads();

        uint32_t aoff = smbase + (uint32_t)((c & 1) * TILE_BYTES);
        uint32_t boff = aoff + ABUF_BYTES;

        #pragma unroll
        for (int ks = 0; ks < 2; ks++) {
            uint32_t af[4][4];
            #pragma unroll
            for (int mi = 0; mi < 4; mi++) {
                int arow = warp_m * 64 + mi * 16 + (q & 1) * 8 + r8;
                int acol = ks * 16 + (q >> 1) * 8;
                ldsm_x4(af[mi], aoff + (uint32_t)(arow * ROWB + acol * 2));
            }
            uint32_t bfr[2][4];
            #pragma unroll
            for (int jp = 0; jp < 2; jp++) {
                int brow = warp_n * 32 + jp * 16 + (q >> 1) * 8 + r8;
                int bcol = ks * 16 + (q & 1) * 8;
                ldsm_x4(bfr[jp], boff + (uint32_t)(brow * ROWB + bcol * 2));
            }
            #pragma unroll
            for (int mi = 0; mi < 4; mi++)
                #pragma unroll
                for (int nj = 0; nj < 4; nj++)
                    mma16816(acc[mi][nj], af[mi], bfr[nj >> 1][(nj & 1) * 2], bfr[nj >> 1][(nj & 1) * 2 + 1]);
        }
        __syncthreads();
    }

    // epilogue: d0,d1 = (row g, cols t*2..+1), d2,d3 = (row g+8, same cols)
    int g = lid >> 2, tg = lid & 3;
    #pragma unroll
    for (int mi = 0; mi < 4; mi++) {
        int m0 = blockIdx.y * 128 + warp_m * 64 + mi * 16 + g;
        #pragma unroll
        for (int nj = 0; nj < 4; nj++) {
            int nb = blockIdx.x * 128 + warp_n * 32 + nj * 8;
            if (nb >= N) continue;
            int n = nb + tg * 2;
            float2 v0 = make_float2(acc[mi][nj][0], acc[mi][nj][1]);
            float2 v1 = make_float2(acc[mi][nj][2], acc[mi][nj][3]);
            if (EPI == 1) {
                float b0 = bias[n], b1 = bias[n + 1];
                v0.x = softplusf(v0.x + b0); v0.y = softplusf(v0.y + b1);
                v1.x = softplusf(v1.x + b0); v1.y = softplusf(v1.y + b1);
            }
            float* p0 = C + (size_t)m0 * ldc + n;
            float* p1 = C + (size_t)(m0 + 8) * ldc + n;
            if (EPI == 2) {
                float2 o0 = *reinterpret_cast<float2*>(p0);
                float2 o1 = *reinterpret_cast<float2*>(p1);
                v0.x += o0.x; v0.y += o0.y; v1.x += o1.x; v1.y += o1.y;
            }
            *reinterpret_cast<float2*>(p0) = v0;
            *reinterpret_cast<float2*>(p1) = v1;
        }
    }
}

// ---------------- copy ------------------------------------------------------
__global__ void copy4_kernel(const float* __restrict__ src, float* __restrict__ dst, int n4) {
    int i = blockIdx.x * blockDim.x + threadIdx.x;
    if (i < n4) reinterpret_cast<float4*>(dst)[i] = reinterpret_cast<const float4*>(src)[i];
}

// ---------------- layernorm -------------------------------------------------
__global__ void layernorm_kernel(const float* __restrict__ src, float* __restrict__ dst,
                                 const float* __restrict__ g, const float* __restrict__ b) {
    int row = blockIdx.x;
    int t = threadIdx.x;
    const float4* s4 = reinterpret_cast<const float4*>(src + (size_t)row * D_MODEL);
    float4 v = s4[t];
    float sum = v.x + v.y + v.z + v.w;
    float sq  = v.x*v.x + v.y*v.y + v.z*v.z + v.w*v.w;
    #pragma unroll
    for (int o = 16; o; o >>= 1) {
        sum += __shfl_xor_sync(0xffffffffu, sum, o);
        sq  += __shfl_xor_sync(0xffffffffu, sq,  o);
    }
    __shared__ float ssum[8], ssq[8];
    int lane = t & 31, wid = t >> 5;
    if (lane == 0) { ssum[wid] = sum; ssq[wid] = sq; }
    __syncthreads();
    float ts = 0.f, tq = 0.f;
    #pragma unroll
    for (int i = 0; i < 8; i++) { ts += ssum[i]; tq += ssq[i]; }
    float mu = ts * (1.f / D_MODEL);
    float var = tq * (1.f / D_MODEL) - mu * mu;
    float rs = rsqrtf(var + LN_EPS);
    float4 gv = reinterpret_cast<const float4*>(g)[t];
    float4 bv = reinterpret_cast<const float4*>(b)[t];
    float4 o;
    o.x = (v.x - mu) * rs * gv.x + bv.x;
    o.y = (v.y - mu) * rs * gv.y + bv.y;
    o.z = (v.z - mu) * rs * gv.z + bv.z;
    o.w = (v.w - mu) * rs * gv.w + bv.w;
    reinterpret_cast<float4*>(dst + (size_t)row * D_MODEL)[t] = o;
}

// ---------------- depthwise causal conv + bias + silu -----------------------
__global__ void conv_silu_kernel(const float* __restrict__ xz,
                                 const float* __restrict__ cw,
                                 const float* __restrict__ cb,
                                 float* __restrict__ xm) {
    int d = blockIdx.x * blockDim.x + threadIdx.x;
    int l = blockIdx.y;
    int b = blockIdx.z;
    float w0 = cw[d*4+0], w1 = cw[d*4+1], w2 = cw[d*4+2], w3 = cw[d*4+3];
    const float* base = xz + (size_t)b * SEQ * (2*D_INNER) + d;
    float acc = cb[d];
    if (l >= 3) acc = fmaf(base[(size_t)(l-3)*(2*D_INNER)], w0, acc);
    if (l >= 2) acc = fmaf(base[(size_t)(l-2)*(2*D_INNER)], w1, acc);
    if (l >= 1) acc = fmaf(base[(size_t)(l-1)*(2*D_INNER)], w2, acc);
    acc = fmaf(base[(size_t)l*(2*D_INNER)], w3, acc);
    xm[((size_t)(b*SEQ) + l) * D_INNER + d] = siluf(acc);
}

// ---------------- selective scan --------------------------------------------
__global__ void scan_kernel(const float* __restrict__ dt,
                            const float* __restrict__ xm,
                            const float* __restrict__ xdbl,
                            const float* __restrict__ xz,
                            const float* __restrict__ A_log,
                            const float* __restrict__ Dskip,
                            float* __restrict__ y) {
    int t = blockIdx.x * blockDim.x + threadIdx.x;
    int s = t & 15;
    int ch = t >> 4;
    int b = ch >> 11;
    int d = ch & (D_INNER - 1);

    float A  = -__expf(A_log[d * D_STATE + s]);
    float Dv = Dskip[d];
    float h = 0.f;

    const float* dt_p = dt   + (size_t)b * SEQ * D_INNER + d;
    const float* xm_p = xm   + (size_t)b * SEQ * D_INNER + d;
    const float* bc_p = xdbl + (size_t)b * SEQ * XDBL_W;
    const float* z_p  = xz   + (size_t)b * SEQ * (2*D_INNER) + D_INNER + d;
    float*       y_p  = y    + (size_t)b * SEQ * D_INNER + d;

    for (int l = 0; l < SEQ; l++) {
        float dtv = dt_p[(size_t)l * D_INNER];
        float xv  = xm_p[(size_t)l * D_INNER];
        float Bv  = bc_p[(size_t)l * XDBL_W + DT_RANK + s];
        float Cv  = bc_p[(size_t)l * XDBL_W + DT_RANK + D_STATE + s];
        float dA  = __expf(dtv * A);
        h = fmaf(h, dA, dtv * Bv * xv);
        float p = h * Cv;
        p += __shfl_xor_sync(0xffffffffu, p, 8);
        p += __shfl_xor_sync(0xffffffffu, p, 4);
        p += __shfl_xor_sync(0xffffffffu, p, 2);
        p += __shfl_xor_sync(0xffffffffu, p, 1);
        if (s == 0) {
            float zv = z_p[(size_t)l * (2*D_INNER)];
            y_p[(size_t)l * D_INNER] = (p + xv * Dv) * siluf(zv);
        }
    }
}

// ---------------- launcher --------------------------------------------------
extern "C" void kernel_launch(void* const* d_in, const int* in_sizes, int n_in,
                              void* d_out, int out_size) {
    const float* x      = (const float*)d_in[0];
    const float* in_w   = (const float*)d_in[1];
    const float* conv_w = (const float*)d_in[2];
    const float* conv_b = (const float*)d_in[3];
    const float* xp_w   = (const float*)d_in[4];
    const float* dt_w   = (const float*)d_in[5];
    const float* dt_b   = (const float*)d_in[6];
    const float* A_log  = (const float*)d_in[7];
    const float* Dskip  = (const float*)d_in[8];
    const float* out_w  = (const float*)d_in[9];
    const float* ln_g   = (const float*)d_in[10];
    const float* ln_b   = (const float*)d_in[11];

    float *gx, *gln, *gxz, *gxm, *gxdbl, *gdt, *gy;
    __nv_bfloat16 *ga3, *gb3;
    cudaGetSymbolAddress((void**)&gx,    g_x);
    cudaGetSymbolAddress((void**)&gln,   g_ln);
    cudaGetSymbolAddress((void**)&gxz,   g_xz);
    cudaGetSymbolAddress((void**)&gxm,   g_xm);
    cudaGetSymbolAddress((void**)&gxdbl, g_xdbl);
    cudaGetSymbolAddress((void**)&gdt,   g_dt);
    cudaGetSymbolAddress((void**)&gy,    g_y);
    cudaGetSymbolAddress((void**)&ga3,   g_a3);
    cudaGetSymbolAddress((void**)&gb3,   g_b3);

    {   // residual stream init
        int n4 = NROWS * D_MODEL / 4;
        copy4_kernel<<<(n4 + 255) / 256, 256>>>(x, gx, n4);
    }

    for (int i = 0; i < N_LAYERS; i++) {
        const float* inw_i = in_w  + (size_t)i * (2*D_INNER) * D_MODEL;
        const float* cw_i  = conv_w + (size_t)i * D_INNER * D_CONV;
        const float* cb_i  = conv_b + (size_t)i * D_INNER;
        const float* xpw_i = xp_w  + (size_t)i * XDBL_W * D_INNER;
        const float* dtw_i = dt_w  + (size_t)i * D_INNER * DT_RANK;
        const float* dtb_i = dt_b  + (size_t)i * D_INNER;
        const float* Al_i  = A_log + (size_t)i * D_INNER * D_STATE;
        const float* Ds_i  = Dskip + (size_t)i * D_INNER;
        const float* ow_i  = out_w + (size_t)i * D_MODEL * D_INNER;

        // 1. layernorm
        layernorm_kernel<<<NROWS, 256>>>(gx, gln, ln_g, ln_b);

        // 2. in_proj: xz[2048,4096] = ln @ in_w^T   (K=1024 -> K3=3072)
        convert_split<0><<<(NROWS   * D_MODEL)/256, 256>>>(gln,   D_MODEL, NROWS,      D_MODEL, ga3);
        convert_split<1><<<(2*D_INNER*D_MODEL)/256, 256>>>(inw_i, D_MODEL, 2*D_INNER,  D_MODEL, gb3);
        mma_gemm<0><<<dim3(2*D_INNER/128, NROWS/128), 256>>>(
            ga3, gb3, gxz, 2*D_INNER, 2*D_INNER, 3*D_MODEL, nullptr);

        // 3. conv + silu
        conv_silu_kernel<<<dim3(D_INNER/256, SEQ, BATCH), 256>>>(gxz, cw_i, cb_i, gxm);

        // 4. x_proj: xdbl[2048,96] = xm @ xp_w^T    (K=2048 -> K3=6144, N pad 128)
        convert_split<0><<<(NROWS * D_INNER)/256, 256>>>(gxm,   D_INNER, NROWS,  D_INNER, ga3);
        convert_split<1><<<(128   * D_INNER)/256, 256>>>(xpw_i, D_INNER, XDBL_W, D_INNER, gb3);
        mma_gemm<0><<<dim3(1, NROWS/128), 256>>>(
            ga3, gb3, gxdbl, XDBL_W, XDBL_W, 3*D_INNER, nullptr);

        // 5. dt: softplus(xdbl[:,:64] @ dt_w^T + dt_b)   (K=64 -> K3=192)
        convert_split<0><<<(NROWS   * DT_RANK)/256, 256>>>(gxdbl, XDBL_W,  NROWS,   DT_RANK, ga3);
        convert_split<1><<<(D_INNER * DT_RANK)/256, 256>>>(dtw_i, DT_RANK, D_INNER, DT_RANK, gb3);
        mma_gemm<1><<<dim3(D_INNER/128, NROWS/128), 256>>>(
            ga3, gb3, gdt, D_INNER, D_INNER, 3*DT_RANK, dtb_i);

        // 6. selective scan + gating
        scan_kernel<<<(BATCH*D_INNER*D_STATE)/256, 256>>>(
            gdt, gxm, gxdbl, gxz, Al_i, Ds_i, gy);

        // 7. out_proj residual: x += y @ out_w^T    (K=2048 -> K3=6144)
        convert_split<0><<<(NROWS   * D_INNER)/256, 256>>>(gy,   D_INNER, NROWS,   D_INNER, ga3);
        convert_split<1><<<(D_MODEL * D_INNER)/256, 256>>>(ow_i, D_INNER, D_MODEL, D_INNER, gb3);
        mma_gemm<2><<<dim3(D_MODEL/128, NROWS/128), 256>>>(
            ga3, gb3, gx, D_MODEL, D_MODEL, 3*D_INNER, nullptr);
    }

    // final layernorm -> output
    layernorm_kernel<<<NROWS, 256>>>(gx, (float*)d_out, ln_g, ln_b);
}

// round 8
// speedup vs baseline: 1.4693x; 1.0617x over previous
#include <cuda_runtime.h>
#include <cuda_bf16.h>
#include <math.h>
#include <cstdint>

#define D_MODEL 1024
#define D_STATE 16
#define D_CONV  4
#define D_INNER 2048
#define DT_RANK 64
#define N_LAYERS 4
#define BATCH 2
#define SEQ 1024
#define NROWS (BATCH*SEQ)            // 2048
#define XDBL_W (DT_RANK + 2*D_STATE) // 96
#define LN_EPS 1e-5f

// ---------------- scratch (device globals; no allocations allowed) ----------
__device__ float g_x   [NROWS * D_MODEL];
__device__ float g_ln  [NROWS * D_MODEL];
__device__ float g_xz  [NROWS * 2 * D_INNER];
__device__ float g_xm  [NROWS * D_INNER];
__device__ float g_xdbl[NROWS * XDBL_W];
__device__ float g_dt  [NROWS * D_INNER];
__device__ float g_y   [NROWS * D_INNER];
__device__ __nv_bfloat16 g_a3[NROWS * 3 * D_INNER];
__device__ __nv_bfloat16 g_b3[2 * D_INNER * 3 * D_MODEL];

// ---------------- helpers ---------------------------------------------------
__device__ __forceinline__ float siluf(float v) { return v / (1.f + __expf(-v)); }
__device__ __forceinline__ float softplusf(float v) {
    return v > 20.f ? v : log1pf(__expf(v));
}
__device__ __forceinline__ uint32_t smem_to_u32(const void* p) {
    uint32_t a;
    asm("{ .reg .u64 t; cvta.to.shared.u64 t, %1; cvt.u32.u64 %0, t; }" : "=r"(a) : "l"(p));
    return a;
}
__device__ __forceinline__ void cp_async16(uint32_t saddr, const void* gaddr) {
    asm volatile("cp.async.cg.shared.global [%0], [%1], 16;" :: "r"(saddr), "l"(gaddr));
}
__device__ __forceinline__ void cp_commit() {
    asm volatile("cp.async.commit_group;" ::: "memory");
}
__device__ __forceinline__ void ldsm_x4(uint32_t (&r)[4], uint32_t addr) {
    asm volatile("ldmatrix.sync.aligned.m8n8.x4.shared.b16 {%0,%1,%2,%3}, [%4];"
                 : "=r"(r[0]), "=r"(r[1]), "=r"(r[2]), "=r"(r[3]) : "r"(addr));
}
__device__ __forceinline__ void mma16816(float* c, const uint32_t* a, uint32_t b0, uint32_t b1) {
    asm volatile(
        "mma.sync.aligned.m16n8k16.row.col.f32.bf16.bf16.f32 "
        "{%0,%1,%2,%3}, {%4,%5,%6,%7}, {%8,%9}, {%0,%1,%2,%3};"
        : "+f"(c[0]), "+f"(c[1]), "+f"(c[2]), "+f"(c[3])
        : "r"(a[0]), "r"(a[1]), "r"(a[2]), "r"(a[3]), "r"(b0), "r"(b1));
}

// ---------------- fused fp32 -> bf16 hi/lo split (act + weight) --------------
// Activation rows (always NROWS valid): dst row = [hi | lo | hi]
// Weight rows (Rvalid valid, Rpad total): dst row = [hi | hi | lo]
__global__ void convert_pair(const float* __restrict__ act, int lda_a, int Ka,
                             __nv_bfloat16* __restrict__ dstA, int actBlocks,
                             const float* __restrict__ wgt, int lda_b, int Rvalid, int Kb,
                             __nv_bfloat16* __restrict__ dstB) {
    if ((int)blockIdx.x < actBlocks) {
        int idx = blockIdx.x * 256 + threadIdx.x;
        int r = idx / Ka, k = idx - r * Ka;
        float v = act[(size_t)r * lda_a + k];
        __nv_bfloat16 hi = __float2bfloat16(v);
        __nv_bfloat16 lo = __float2bfloat16(v - __bfloat162float(hi));
        size_t base = (size_t)r * 3 * Ka;
        dstA[base + k] = hi; dstA[base + Ka + k] = lo; dstA[base + 2*Ka + k] = hi;
    } else {
        int idx = (blockIdx.x - actBlocks) * 256 + threadIdx.x;
        int r = idx / Kb, k = idx - r * Kb;
        __nv_bfloat16 hi = __float2bfloat16(0.f), lo = hi;
        if (r < Rvalid) {
            float v = wgt[(size_t)r * lda_b + k];
            hi = __float2bfloat16(v);
            lo = __float2bfloat16(v - __bfloat162float(hi));
        }
        size_t base = (size_t)r * 3 * Kb;
        dstB[base + k] = hi; dstB[base + Kb + k] = hi; dstB[base + 2*Kb + k] = lo;
    }
}

// ---------------- HMMA GEMM: C[M,N] = A3[M,K3] @ B3[N,K3]^T ------------------
// CTA tile 128x128, BK=64, 256 threads (8 warps, 2x4), warp tile 64x32.
// 3-stage cp.async pipeline, one __syncthreads per k-iteration.
// Row stride 144B (64 bf16 data + 8 pad) -> conflict-free ldmatrix.
// EPI: 0 plain, 1 softplus(acc+bias[n]), 2 C += acc
#define ROWB 144
#define ABYTES 18432            // 128*144
#define STAGE_BYTES 36864       // A+B per stage
#define NSTAGE 3
#define SMEM_DYN (NSTAGE*STAGE_BYTES)
template<int EPI>
__global__ void __launch_bounds__(256, 2)
mma_gemm(const __nv_bfloat16* __restrict__ A3, const __nv_bfloat16* __restrict__ B3,
         float* __restrict__ C, int ldc, int N, int K3, const float* __restrict__ bias) {
    extern __shared__ __align__(128) unsigned char sm[];
    uint32_t smbase = smem_to_u32(sm);

    int tid = threadIdx.x;
    int wid = tid >> 5, lid = tid & 31;
    int warp_m = wid >> 2;           // 0..1 -> m offset *64
    int warp_n = wid & 3;            // 0..3 -> n offset *32
    int q = lid >> 3, r8 = lid & 7;

    const __nv_bfloat16* Abase = A3 + (size_t)(blockIdx.y * 128) * K3;
    const __nv_bfloat16* Bbase = B3 + (size_t)(blockIdx.x * 128) * K3;

    float acc[4][4][4];
    #pragma unroll
    for (int i = 0; i < 4; i++)
        #pragma unroll
        for (int j = 0; j < 4; j++)
            #pragma unroll
            for (int v = 0; v < 4; v++) acc[i][j][v] = 0.f;

    int ktiles = K3 >> 6;   // BK=64

    // loader: 4 chunks of 16B per operand per thread per stage
    #define LOAD_STAGE(stg, kk) do { \
        uint32_t sb_ = smbase + (uint32_t)((stg) * STAGE_BYTES); \
        _Pragma("unroll") \
        for (int g_ = 0; g_ < 4; g_++) { \
            int ch_ = g_ * 256 + tid; \
            int row_ = ch_ >> 3, c16_ = ch_ & 7; \
            uint32_t sa_ = sb_ + (uint32_t)(row_ * ROWB + c16_ * 16); \
            cp_async16(sa_,          Abase + (size_t)row_ * K3 + (kk) + c16_ * 8); \
            cp_async16(sa_ + ABYTES, Bbase + (size_t)row_ * K3 + (kk) + c16_ * 8); \
        } \
    } while (0)

    // prologue: stages 0 and 1
    LOAD_STAGE(0, 0);
    cp_commit();
    if (ktiles > 1) LOAD_STAGE(1, 64);
    cp_commit();

    for (int c = 0; c < ktiles; c++) {
        asm volatile("cp.async.wait_group 1;" ::: "memory");
        __syncthreads();
        // issue stage c+2 into buffer (c+2)%3 (freed by the barrier above)
        if (c + 2 < ktiles) LOAD_STAGE((c + 2) % NSTAGE, (c + 2) * 64);
        cp_commit();

        uint32_t aoff = smbase + (uint32_t)((c % NSTAGE) * STAGE_BYTES);
        uint32_t boff = aoff + ABYTES;
        #pragma unroll
        for (int ks = 0; ks < 4; ks++) {
            uint32_t af[4][4];
            #pragma unroll
            for (int mi = 0; mi < 4; mi++) {
                int arow = warp_m * 64 + mi * 16 + (q & 1) * 8 + r8;
                int acol = ks * 16 + (q >> 1) * 8;
                ldsm_x4(af[mi], aoff + (uint32_t)(arow * ROWB + acol * 2));
            }
            uint32_t bfr[2][4];
            #pragma unroll
            for (int jp = 0; jp < 2; jp++) {
                int brow = warp_n * 32 + jp * 16 + (q >> 1) * 8 + r8;
                int bcol = ks * 16 + (q & 1) * 8;
                ldsm_x4(bfr[jp], boff + (uint32_t)(brow * ROWB + bcol * 2));
            }
            #pragma unroll
            for (int mi = 0; mi < 4; mi++)
                #pragma unroll
                for (int nj = 0; nj < 4; nj++)
                    mma16816(acc[mi][nj], af[mi], bfr[nj >> 1][(nj & 1) * 2], bfr[nj >> 1][(nj & 1) * 2 + 1]);
        }
    }

    // epilogue
    int g = lid >> 2, tg = lid & 3;
    #pragma unroll
    for (int mi = 0; mi < 4; mi++) {
        int m0 = blockIdx.y * 128 + warp_m * 64 + mi * 16 + g;
        #pragma unroll
        for (int nj = 0; nj < 4; nj++) {
            int nb = blockIdx.x * 128 + warp_n * 32 + nj * 8;
            if (nb >= N) continue;
            int n = nb + tg * 2;
            float2 v0 = make_float2(acc[mi][nj][0], acc[mi][nj][1]);
            float2 v1 = make_float2(acc[mi][nj][2], acc[mi][nj][3]);
            if (EPI == 1) {
                float b0 = bias[n], b1 = bias[n + 1];
                v0.x = softplusf(v0.x + b0); v0.y = softplusf(v0.y + b1);
                v1.x = softplusf(v1.x + b0); v1.y = softplusf(v1.y + b1);
            }
            float* p0 = C + (size_t)m0 * ldc + n;
            float* p1 = C + (size_t)(m0 + 8) * ldc + n;
            if (EPI == 2) {
                float2 o0 = *reinterpret_cast<float2*>(p0);
                float2 o1 = *reinterpret_cast<float2*>(p1);
                v0.x += o0.x; v0.y += o0.y; v1.x += o1.x; v1.y += o1.y;
            }
            *reinterpret_cast<float2*>(p0) = v0;
            *reinterpret_cast<float2*>(p1) = v1;
        }
    }
    #undef LOAD_STAGE
}

// ---------------- copy ------------------------------------------------------
__global__ void copy4_kernel(const float* __restrict__ src, float* __restrict__ dst, int n4) {
    int i = blockIdx.x * blockDim.x + threadIdx.x;
    if (i < n4) reinterpret_cast<float4*>(dst)[i] = reinterpret_cast<const float4*>(src)[i];
}

// ---------------- layernorm -------------------------------------------------
__global__ void layernorm_kernel(const float* __restrict__ src, float* __restrict__ dst,
                                 const float* __restrict__ g, const float* __restrict__ b) {
    int row = blockIdx.x;
    int t = threadIdx.x;
    const float4* s4 = reinterpret_cast<const float4*>(src + (size_t)row * D_MODEL);
    float4 v = s4[t];
    float sum = v.x + v.y + v.z + v.w;
    float sq  = v.x*v.x + v.y*v.y + v.z*v.z + v.w*v.w;
    #pragma unroll
    for (int o = 16; o; o >>= 1) {
        sum += __shfl_xor_sync(0xffffffffu, sum, o);
        sq  += __shfl_xor_sync(0xffffffffu, sq,  o);
    }
    __shared__ float ssum[8], ssq[8];
    int lane = t & 31, wid = t >> 5;
    if (lane == 0) { ssum[wid] = sum; ssq[wid] = sq; }
    __syncthreads();
    float ts = 0.f, tq = 0.f;
    #pragma unroll
    for (int i = 0; i < 8; i++) { ts += ssum[i]; tq += ssq[i]; }
    float mu = ts * (1.f / D_MODEL);
    float var = tq * (1.f / D_MODEL) - mu * mu;
    float rs = rsqrtf(var + LN_EPS);
    float4 gv = reinterpret_cast<const float4*>(g)[t];
    float4 bv = reinterpret_cast<const float4*>(b)[t];
    float4 o;
    o.x = (v.x - mu) * rs * gv.x + bv.x;
    o.y = (v.y - mu) * rs * gv.y + bv.y;
    o.z = (v.z - mu) * rs * gv.z + bv.z;
    o.w = (v.w - mu) * rs * gv.w + bv.w;
    reinterpret_cast<float4*>(dst + (size_t)row * D_MODEL)[t] = o;
}

// ---------------- depthwise causal conv + bias + silu -----------------------
__global__ void conv_silu_kernel(const float* __restrict__ xz,
                                 const float* __restrict__ cw,
                                 const float* __restrict__ cb,
                                 float* __restrict__ xm) {
    int d = blockIdx.x * blockDim.x + threadIdx.x;
    int l = blockIdx.y;
    int b = blockIdx.z;
    float w0 = cw[d*4+0], w1 = cw[d*4+1], w2 = cw[d*4+2], w3 = cw[d*4+3];
    const float* base = xz + (size_t)b * SEQ * (2*D_INNER) + d;
    float acc = cb[d];
    if (l >= 3) acc = fmaf(base[(size_t)(l-3)*(2*D_INNER)], w0, acc);
    if (l >= 2) acc = fmaf(base[(size_t)(l-2)*(2*D_INNER)], w1, acc);
    if (l >= 1) acc = fmaf(base[(size_t)(l-1)*(2*D_INNER)], w2, acc);
    acc = fmaf(base[(size_t)l*(2*D_INNER)], w3, acc);
    xm[((size_t)(b*SEQ) + l) * D_INNER + d] = siluf(acc);
}

// ---------------- selective scan --------------------------------------------
__global__ void scan_kernel(const float* __restrict__ dt,
                            const float* __restrict__ xm,
                            const float* __restrict__ xdbl,
                            const float* __restrict__ xz,
                            const float* __restrict__ A_log,
                            const float* __restrict__ Dskip,
                            float* __restrict__ y) {
    int t = blockIdx.x * blockDim.x + threadIdx.x;
    int s = t & 15;
    int ch = t >> 4;
    int b = ch >> 11;
    int d = ch & (D_INNER - 1);

    float A  = -__expf(A_log[d * D_STATE + s]);
    float Dv = Dskip[d];
    float h = 0.f;

    const float* dt_p = dt   + (size_t)b * SEQ * D_INNER + d;
    const float* xm_p = xm   + (size_t)b * SEQ * D_INNER + d;
    const float* bc_p = xdbl + (size_t)b * SEQ * XDBL_W;
    const float* z_p  = xz   + (size_t)b * SEQ * (2*D_INNER) + D_INNER + d;
    float*       y_p  = y    + (size_t)b * SEQ * D_INNER + d;

    for (int l = 0; l < SEQ; l++) {
        float dtv = dt_p[(size_t)l * D_INNER];
        float xv  = xm_p[(size_t)l * D_INNER];
        float Bv  = bc_p[(size_t)l * XDBL_W + DT_RANK + s];
        float Cv  = bc_p[(size_t)l * XDBL_W + DT_RANK + D_STATE + s];
        float dA  = __expf(dtv * A);
        h = fmaf(h, dA, dtv * Bv * xv);
        float p = h * Cv;
        p += __shfl_xor_sync(0xffffffffu, p, 8);
        p += __shfl_xor_sync(0xffffffffu, p, 4);
        p += __shfl_xor_sync(0xffffffffu, p, 2);
        p += __shfl_xor_sync(0xffffffffu, p, 1);
        if (s == 0) {
            float zv = z_p[(size_t)l * (2*D_INNER)];
            y_p[(size_t)l * D_INNER] = (p + xv * Dv) * siluf(zv);
        }
    }
}

// ---------------- launcher --------------------------------------------------
extern "C" void kernel_launch(void* const* d_in, const int* in_sizes, int n_in,
                              void* d_out, int out_size) {
    const float* x      = (const float*)d_in[0];
    const float* in_w   = (const float*)d_in[1];
    const float* conv_w = (const float*)d_in[2];
    const float* conv_b = (const float*)d_in[3];
    const float* xp_w   = (const float*)d_in[4];
    const float* dt_w   = (const float*)d_in[5];
    const float* dt_b   = (const float*)d_in[6];
    const float* A_log  = (const float*)d_in[7];
    const float* Dskip  = (const float*)d_in[8];
    const float* out_w  = (const float*)d_in[9];
    const float* ln_g   = (const float*)d_in[10];
    const float* ln_b   = (const float*)d_in[11];

    float *gx, *gln, *gxz, *gxm, *gxdbl, *gdt, *gy;
    __nv_bfloat16 *ga3, *gb3;
    cudaGetSymbolAddress((void**)&gx,    g_x);
    cudaGetSymbolAddress((void**)&gln,   g_ln);
    cudaGetSymbolAddress((void**)&gxz,   g_xz);
    cudaGetSymbolAddress((void**)&gxm,   g_xm);
    cudaGetSymbolAddress((void**)&gxdbl, g_xdbl);
    cudaGetSymbolAddress((void**)&gdt,   g_dt);
    cudaGetSymbolAddress((void**)&gy,    g_y);
    cudaGetSymbolAddress((void**)&ga3,   g_a3);
    cudaGetSymbolAddress((void**)&gb3,   g_b3);

    cudaFuncSetAttribute(mma_gemm<0>, cudaFuncAttributeMaxDynamicSharedMemorySize, SMEM_DYN);
    cudaFuncSetAttribute(mma_gemm<1>, cudaFuncAttributeMaxDynamicSharedMemorySize, SMEM_DYN);
    cudaFuncSetAttribute(mma_gemm<2>, cudaFuncAttributeMaxDynamicSharedMemorySize, SMEM_DYN);

    {   // residual stream init
        int n4 = NROWS * D_MODEL / 4;
        copy4_kernel<<<(n4 + 255) / 256, 256>>>(x, gx, n4);
    }

    for (int i = 0; i < N_LAYERS; i++) {
        const float* inw_i = in_w  + (size_t)i * (2*D_INNER) * D_MODEL;
        const float* cw_i  = conv_w + (size_t)i * D_INNER * D_CONV;
        const float* cb_i  = conv_b + (size_t)i * D_INNER;
        const float* xpw_i = xp_w  + (size_t)i * XDBL_W * D_INNER;
        const float* dtw_i = dt_w  + (size_t)i * D_INNER * DT_RANK;
        const float* dtb_i = dt_b  + (size_t)i * D_INNER;
        const float* Al_i  = A_log + (size_t)i * D_INNER * D_STATE;
        const float* Ds_i  = Dskip + (size_t)i * D_INNER;
        const float* ow_i  = out_w + (size_t)i * D_MODEL * D_INNER;

        // 1. layernorm
        layernorm_kernel<<<NROWS, 256>>>(gx, gln, ln_g, ln_b);

        // 2. in_proj: xz[2048,4096] = ln @ in_w^T   (K=1024 -> K3=3072)
        {
            int ab = (NROWS * D_MODEL) / 256, wb = (2*D_INNER * D_MODEL) / 256;
            convert_pair<<<ab + wb, 256>>>(gln, D_MODEL, D_MODEL, ga3, ab,
                                           inw_i, D_MODEL, 2*D_INNER, D_MODEL, gb3);
            mma_gemm<0><<<dim3(2*D_INNER/128, NROWS/128), 256, SMEM_DYN>>>(
                ga3, gb3, gxz, 2*D_INNER, 2*D_INNER, 3*D_MODEL, nullptr);
        }

        // 3. conv + silu
        conv_silu_kernel<<<dim3(D_INNER/256, SEQ, BATCH), 256>>>(gxz, cw_i, cb_i, gxm);

        // 4. x_proj: xdbl[2048,96] = xm @ xp_w^T    (K=2048 -> K3=6144, N pad 128)
        {
            int ab = (NROWS * D_INNER) / 256, wb = (128 * D_INNER) / 256;
            convert_pair<<<ab + wb, 256>>>(gxm, D_INNER, D_INNER, ga3, ab,
                                           xpw_i, D_INNER, XDBL_W, D_INNER, gb3);
            mma_gemm<0><<<dim3(1, NROWS/128), 256, SMEM_DYN>>>(
                ga3, gb3, gxdbl, XDBL_W, XDBL_W, 3*D_INNER, nullptr);
        }

        // 5. dt: softplus(xdbl[:,:64] @ dt_w^T + dt_b)   (K=64 -> K3=192)
        {
            int ab = (NROWS * DT_RANK) / 256, wb = (D_INNER * DT_RANK) / 256;
            convert_pair<<<ab + wb, 256>>>(gxdbl, XDBL_W, DT_RANK, ga3, ab,
                                           dtw_i, DT_RANK, D_INNER, DT_RANK, gb3);
            mma_gemm<1><<<dim3(D_INNER/128, NROWS/128), 256, SMEM_DYN>>>(
                ga3, gb3, gdt, D_INNER, D_INNER, 3*DT_RANK, dtb_i);
        }

        // 6. selective scan + gating
        scan_kernel<<<(BATCH*D_INNER*D_STATE)/256, 256>>>(
            gdt, gxm, gxdbl, gxz, Al_i, Ds_i, gy);

        // 7. out_proj residual: x += y @ out_w^T    (K=2048 -> K3=6144)
        {
            int ab = (NROWS * D_INNER) / 256, wb = (D_MODEL * D_INNER) / 256;
            convert_pair<<<ab + wb, 256>>>(gy, D_INNER, D_INNER, ga3, ab,
                                           ow_i, D_INNER, D_MODEL, D_INNER, gb3);
            mma_gemm<2><<<dim3(D_MODEL/128, NROWS/128), 256, SMEM_DYN>>>(
                ga3, gb3, gx, D_MODEL, D_MODEL, 3*D_INNER, nullptr);
        }
    }

    // final layernorm -> output
    layernorm_kernel<<<NROWS, 256>>>(gx, (float*)d_out, ln_g, ln_b);
}

// round 9
// speedup vs baseline: 2.5118x; 1.7095x over previous
#include <cuda_runtime.h>
#include <cuda_bf16.h>
#include <math.h>
#include <cstdint>

#define D_MODEL 1024
#define D_STATE 16
#define D_CONV  4
#define D_INNER 2048
#define DT_RANK 64
#define N_LAYERS 4
#define BATCH 2
#define SEQ 1024
#define NROWS (BATCH*SEQ)            // 2048
#define XDBL_W (DT_RANK + 2*D_STATE) // 96
#define LN_EPS 1e-5f
#define NCHUNK 4
#define CHUNK (SEQ/NCHUNK)           // 256
#define NCH (BATCH*D_INNER*D_STATE)  // 65536

// ---------------- scratch (device globals; no allocations allowed) ----------
__device__ float g_x   [NROWS * D_MODEL];
__device__ float g_ln  [NROWS * D_MODEL];
__device__ float g_xz  [NROWS * 2 * D_INNER];
__device__ float g_xm  [NROWS * D_INNER];
__device__ float g_xdbl[NROWS * XDBL_W];
__device__ float g_dt  [NROWS * D_INNER];
__device__ float g_y   [NROWS * D_INNER];
__device__ float g_sA  [3 * NCH];
__device__ float g_sB  [3 * NCH];
__device__ __nv_bfloat16 g_a3[NROWS * 3 * D_INNER];
__device__ __nv_bfloat16 g_b3[2 * D_INNER * 3 * D_MODEL];

// ---------------- helpers ---------------------------------------------------
__device__ __forceinline__ float siluf(float v) { return v / (1.f + __expf(-v)); }
__device__ __forceinline__ float softplusf(float v) {
    return v > 20.f ? v : log1pf(__expf(v));
}
__device__ __forceinline__ uint32_t smem_to_u32(const void* p) {
    uint32_t a;
    asm("{ .reg .u64 t; cvta.to.shared.u64 t, %1; cvt.u32.u64 %0, t; }" : "=r"(a) : "l"(p));
    return a;
}
__device__ __forceinline__ void cp_async16(uint32_t saddr, const void* gaddr) {
    asm volatile("cp.async.cg.shared.global [%0], [%1], 16;" :: "r"(saddr), "l"(gaddr));
}
__device__ __forceinline__ void cp_commit() {
    asm volatile("cp.async.commit_group;" ::: "memory");
}
__device__ __forceinline__ void ldsm_x4(uint32_t (&r)[4], uint32_t addr) {
    asm volatile("ldmatrix.sync.aligned.m8n8.x4.shared.b16 {%0,%1,%2,%3}, [%4];"
                 : "=r"(r[0]), "=r"(r[1]), "=r"(r[2]), "=r"(r[3]) : "r"(addr));
}
__device__ __forceinline__ void mma16816(float* c, const uint32_t* a, uint32_t b0, uint32_t b1) {
    asm volatile(
        "mma.sync.aligned.m16n8k16.row.col.f32.bf16.bf16.f32 "
        "{%0,%1,%2,%3}, {%4,%5,%6,%7}, {%8,%9}, {%0,%1,%2,%3};"
        : "+f"(c[0]), "+f"(c[1]), "+f"(c[2]), "+f"(c[3])
        : "r"(a[0]), "r"(a[1]), "r"(a[2]), "r"(a[3]), "r"(b0), "r"(b1));
}

// ---------------- fused fp32 -> bf16 hi/lo split (act + weight) --------------
__global__ void convert_pair(const float* __restrict__ act, int lda_a, int Ka,
                             __nv_bfloat16* __restrict__ dstA, int actBlocks,
                             const float* __restrict__ wgt, int lda_b, int Rvalid, int Kb,
                             __nv_bfloat16* __restrict__ dstB) {
    if ((int)blockIdx.x < actBlocks) {
        int idx = blockIdx.x * 256 + threadIdx.x;
        int r = idx / Ka, k = idx - r * Ka;
        float v = act[(size_t)r * lda_a + k];
        __nv_bfloat16 hi = __float2bfloat16(v);
        __nv_bfloat16 lo = __float2bfloat16(v - __bfloat162float(hi));
        size_t base = (size_t)r * 3 * Ka;
        dstA[base + k] = hi; dstA[base + Ka + k] = lo; dstA[base + 2*Ka + k] = hi;
    } else {
        int idx = (blockIdx.x - actBlocks) * 256 + threadIdx.x;
        int r = idx / Kb, k = idx - r * Kb;
        __nv_bfloat16 hi = __float2bfloat16(0.f), lo = hi;
        if (r < Rvalid) {
            float v = wgt[(size_t)r * lda_b + k];
            hi = __float2bfloat16(v);
            lo = __float2bfloat16(v - __bfloat162float(hi));
        }
        size_t base = (size_t)r * 3 * Kb;
        dstB[base + k] = hi; dstB[base + Kb + k] = hi; dstB[base + 2*Kb + k] = lo;
    }
}

// ---------------- HMMA GEMM: C[M,N] = A3[M,K3] @ B3[N,K3]^T ------------------
// CTA tile 128x64, BK=32, 256 threads (8 warps, 4x2), warp tile 32x32.
// 3-stage cp.async pipeline, 4 CTAs/SM (50% occ). Row stride 80B.
// EPI: 0 plain, 1 softplus(acc+bias[n]), 2 C += acc
#define ROWB 80
#define ABYTES (128*ROWB)                 // 10240
#define STAGE_BYTES ((128+64)*ROWB)       // 15360
#define NSTAGE 3
#define SMEM_DYN (NSTAGE*STAGE_BYTES)     // 46080
template<int EPI>
__global__ void __launch_bounds__(256, 4)
mma_gemm(const __nv_bfloat16* __restrict__ A3, const __nv_bfloat16* __restrict__ B3,
         float* __restrict__ C, int ldc, int N, int K3, const float* __restrict__ bias) {
    extern __shared__ __align__(128) unsigned char sm[];
    uint32_t smbase = smem_to_u32(sm);

    int tid = threadIdx.x;
    int wid = tid >> 5, lid = tid & 31;
    int warp_m = wid & 3;            // *32 in M
    int warp_n = wid >> 2;           // *32 in N
    int q = lid >> 3, r8 = lid & 7;

    const __nv_bfloat16* Abase = A3 + (size_t)(blockIdx.y * 128) * K3;
    const __nv_bfloat16* Bbase = B3 + (size_t)(blockIdx.x * 64) * K3;

    float acc[2][4][4];
    #pragma unroll
    for (int i = 0; i < 2; i++)
        #pragma unroll
        for (int j = 0; j < 4; j++)
            #pragma unroll
            for (int v = 0; v < 4; v++) acc[i][j][v] = 0.f;

    int ktiles = K3 >> 5;   // BK=32

    // A: 512 16B-chunks, B: 256 chunks per stage
    #define LOAD_STAGE(stg, kk) do { \
        uint32_t sb_ = smbase + (uint32_t)((stg) * STAGE_BYTES); \
        _Pragma("unroll") \
        for (int g_ = 0; g_ < 2; g_++) { \
            int ch_ = g_ * 256 + tid; \
            int row_ = ch_ >> 2, c16_ = ch_ & 3; \
            cp_async16(sb_ + (uint32_t)(row_ * ROWB + c16_ * 16), \
                       Abase + (size_t)row_ * K3 + (kk) + c16_ * 8); \
        } \
        { \
            int row_ = tid >> 2, c16_ = tid & 3; \
            cp_async16(sb_ + ABYTES + (uint32_t)(row_ * ROWB + c16_ * 16), \
                       Bbase + (size_t)row_ * K3 + (kk) + c16_ * 8); \
        } \
    } while (0)

    LOAD_STAGE(0, 0);
    cp_commit();
    if (ktiles > 1) LOAD_STAGE(1, 32);
    cp_commit();

    for (int c = 0; c < ktiles; c++) {
        asm volatile("cp.async.wait_group 1;" ::: "memory");
        __syncthreads();
        if (c + 2 < ktiles) LOAD_STAGE((c + 2) % NSTAGE, (c + 2) * 32);
        cp_commit();

        uint32_t aoff = smbase + (uint32_t)((c % NSTAGE) * STAGE_BYTES);
        uint32_t boff = aoff + ABYTES;
        #pragma unroll
        for (int ks = 0; ks < 2; ks++) {
            uint32_t af[2][4];
            #pragma unroll
            for (int mi = 0; mi < 2; mi++) {
                int arow = warp_m * 32 + mi * 16 + (q & 1) * 8 + r8;
                int acol = ks * 16 + (q >> 1) * 8;
                ldsm_x4(af[mi], aoff + (uint32_t)(arow * ROWB + acol * 2));
            }
            uint32_t bfr[2][4];
            #pragma unroll
            for (int jp = 0; jp < 2; jp++) {
                int brow = warp_n * 32 + jp * 16 + (q >> 1) * 8 + r8;
                int bcol = ks * 16 + (q & 1) * 8;
                ldsm_x4(bfr[jp], boff + (uint32_t)(brow * ROWB + bcol * 2));
            }
            #pragma unroll
            for (int mi = 0; mi < 2; mi++)
                #pragma unroll
                for (int nj = 0; nj < 4; nj++)
                    mma16816(acc[mi][nj], af[mi], bfr[nj >> 1][(nj & 1) * 2], bfr[nj >> 1][(nj & 1) * 2 + 1]);
        }
    }

    // epilogue
    int g = lid >> 2, tg = lid & 3;
    #pragma unroll
    for (int mi = 0; mi < 2; mi++) {
        int m0 = blockIdx.y * 128 + warp_m * 32 + mi * 16 + g;
        #pragma unroll
        for (int nj = 0; nj < 4; nj++) {
            int nb = blockIdx.x * 64 + warp_n * 32 + nj * 8;
            if (nb >= N) continue;
            int n = nb + tg * 2;
            float2 v0 = make_float2(acc[mi][nj][0], acc[mi][nj][1]);
            float2 v1 = make_float2(acc[mi][nj][2], acc[mi][nj][3]);
            if (EPI == 1) {
                float b0 = bias[n], b1 = bias[n + 1];
                v0.x = softplusf(v0.x + b0); v0.y = softplusf(v0.y + b1);
                v1.x = softplusf(v1.x + b0); v1.y = softplusf(v1.y + b1);
            }
            float* p0 = C + (size_t)m0 * ldc + n;
            float* p1 = C + (size_t)(m0 + 8) * ldc + n;
            if (EPI == 2) {
                float2 o0 = *reinterpret_cast<float2*>(p0);
                float2 o1 = *reinterpret_cast<float2*>(p1);
                v0.x += o0.x; v0.y += o0.y; v1.x += o1.x; v1.y += o1.y;
            }
            *reinterpret_cast<float2*>(p0) = v0;
            *reinterpret_cast<float2*>(p1) = v1;
        }
    }
    #undef LOAD_STAGE
}

// ---------------- copy ------------------------------------------------------
__global__ void copy4_kernel(const float* __restrict__ src, float* __restrict__ dst, int n4) {
    int i = blockIdx.x * blockDim.x + threadIdx.x;
    if (i < n4) reinterpret_cast<float4*>(dst)[i] = reinterpret_cast<const float4*>(src)[i];
}

// ---------------- layernorm -------------------------------------------------
__global__ void layernorm_kernel(const float* __restrict__ src, float* __restrict__ dst,
                                 const float* __restrict__ g, const float* __restrict__ b) {
    int row = blockIdx.x;
    int t = threadIdx.x;
    const float4* s4 = reinterpret_cast<const float4*>(src + (size_t)row * D_MODEL);
    float4 v = s4[t];
    float sum = v.x + v.y + v.z + v.w;
    float sq  = v.x*v.x + v.y*v.y + v.z*v.z + v.w*v.w;
    #pragma unroll
    for (int o = 16; o; o >>= 1) {
        sum += __shfl_xor_sync(0xffffffffu, sum, o);
        sq  += __shfl_xor_sync(0xffffffffu, sq,  o);
    }
    __shared__ float ssum[8], ssq[8];
    int lane = t & 31, wid = t >> 5;
    if (lane == 0) { ssum[wid] = sum; ssq[wid] = sq; }
    __syncthreads();
    float ts = 0.f, tq = 0.f;
    #pragma unroll
    for (int i = 0; i < 8; i++) { ts += ssum[i]; tq += ssq[i]; }
    float mu = ts * (1.f / D_MODEL);
    float var = tq * (1.f / D_MODEL) - mu * mu;
    float rs = rsqrtf(var + LN_EPS);
    float4 gv = reinterpret_cast<const float4*>(g)[t];
    float4 bv = reinterpret_cast<const float4*>(b)[t];
    float4 o;
    o.x = (v.x - mu) * rs * gv.x + bv.x;
    o.y = (v.y - mu) * rs * gv.y + bv.y;
    o.z = (v.z - mu) * rs * gv.z + bv.z;
    o.w = (v.w - mu) * rs * gv.w + bv.w;
    reinterpret_cast<float4*>(dst + (size_t)row * D_MODEL)[t] = o;
}

// ---------------- depthwise causal conv + bias + silu -----------------------
__global__ void conv_silu_kernel(const float* __restrict__ xz,
                                 const float* __restrict__ cw,
                                 const float* __restrict__ cb,
                                 float* __restrict__ xm) {
    int d = blockIdx.x * blockDim.x + threadIdx.x;
    int l = blockIdx.y;
    int b = blockIdx.z;
    float w0 = cw[d*4+0], w1 = cw[d*4+1], w2 = cw[d*4+2], w3 = cw[d*4+3];
    const float* base = xz + (size_t)b * SEQ * (2*D_INNER) + d;
    float acc = cb[d];
    if (l >= 3) acc = fmaf(base[(size_t)(l-3)*(2*D_INNER)], w0, acc);
    if (l >= 2) acc = fmaf(base[(size_t)(l-2)*(2*D_INNER)], w1, acc);
    if (l >= 1) acc = fmaf(base[(size_t)(l-1)*(2*D_INNER)], w2, acc);
    acc = fmaf(base[(size_t)l*(2*D_INNER)], w3, acc);
    xm[((size_t)(b*SEQ) + l) * D_INNER + d] = siluf(acc);
}

// ---------------- selective scan: chunked 2-pass -----------------------------
// Pass 1: chunks 0..2 scan from h=0, emit (prod dA, h_end) per (chunk, ch, s).
__global__ void scan_pass1(const float* __restrict__ dt,
                           const float* __restrict__ xm,
                           const float* __restrict__ xdbl,
                           const float* __restrict__ A_log,
                           float* __restrict__ sA, float* __restrict__ sB) {
    int idx = blockIdx.x * blockDim.x + threadIdx.x;   // 3*NCH threads
    int s = idx & 15;
    int ch = (idx >> 4) & (BATCH*D_INNER - 1);
    int chunk = idx >> 20;                              // NCH=65536 -> >>16 of (idx>>4)... careful
    chunk = idx / NCH;                                  // 0..2
    int rem = idx - chunk * NCH;
    s = rem & 15;
    ch = rem >> 4;
    int b = ch >> 11;
    int d = ch & (D_INNER - 1);

    float A  = -__expf(A_log[d * D_STATE + s]);
    float aP = 1.f, h = 0.f;

    const float* dt_p = dt   + (size_t)b * SEQ * D_INNER + d;
    const float* xm_p = xm   + (size_t)b * SEQ * D_INNER + d;
    const float* bc_p = xdbl + (size_t)b * SEQ * XDBL_W + DT_RANK + s;

    int l0 = chunk * CHUNK;
    #pragma unroll 4
    for (int l = l0; l < l0 + CHUNK; l++) {
        float dtv = dt_p[(size_t)l * D_INNER];
        float xv  = xm_p[(size_t)l * D_INNER];
        float Bv  = bc_p[(size_t)l * XDBL_W];
        float dA  = __expf(dtv * A);
        aP *= dA;
        h = fmaf(h, dA, dtv * Bv * xv);
    }
    sA[idx] = aP;
    sB[idx] = h;
}

// Pass 2: compute h_start from chunk prefixes, rescan with full y epilogue.
__global__ void scan_pass2(const float* __restrict__ dt,
                           const float* __restrict__ xm,
                           const float* __restrict__ xdbl,
                           const float* __restrict__ xz,
                           const float* __restrict__ A_log,
                           const float* __restrict__ Dskip,
                           const float* __restrict__ sA, const float* __restrict__ sB,
                           float* __restrict__ y) {
    int idx = blockIdx.x * blockDim.x + threadIdx.x;   // 4*NCH threads
    int chunk = idx / NCH;                              // 0..3
    int rem = idx - chunk * NCH;
    int s = rem & 15;
    int ch = rem >> 4;
    int b = ch >> 11;
    int d = ch & (D_INNER - 1);

    float A  = -__expf(A_log[d * D_STATE + s]);
    float Dv = Dskip[d];

    float h = 0.f;
    #pragma unroll
    for (int c = 0; c < 3; c++) {
        if (c < chunk) {
            int slot = c * NCH + rem;
            h = fmaf(h, sA[slot] * 0.f + sA[slot], 0.f) ; // placeholder avoided below
        }
    }
    // (re-do cleanly: affine combine of predecessors)
    h = 0.f;
    for (int c = 0; c < chunk; c++) {
        int slot = c * NCH + rem;
        h = fmaf(sA[slot], h, sB[slot]);
    }

    const float* dt_p = dt   + (size_t)b * SEQ * D_INNER + d;
    const float* xm_p = xm   + (size_t)b * SEQ * D_INNER + d;
    const float* bc_p = xdbl + (size_t)b * SEQ * XDBL_W;
    const float* z_p  = xz   + (size_t)b * SEQ * (2*D_INNER) + D_INNER + d;
    float*       y_p  = y    + (size_t)b * SEQ * D_INNER + d;

    int l0 = chunk * CHUNK;
    #pragma unroll 2
    for (int l = l0; l < l0 + CHUNK; l++) {
        float dtv = dt_p[(size_t)l * D_INNER];
        float xv  = xm_p[(size_t)l * D_INNER];
        float Bv  = bc_p[(size_t)l * XDBL_W + DT_RANK + s];
        float Cv  = bc_p[(size_t)l * XDBL_W + DT_RANK + D_STATE + s];
        float dA  = __expf(dtv * A);
        h = fmaf(h, dA, dtv * Bv * xv);
        float p = h * Cv;
        p += __shfl_xor_sync(0xffffffffu, p, 8);
        p += __shfl_xor_sync(0xffffffffu, p, 4);
        p += __shfl_xor_sync(0xffffffffu, p, 2);
        p += __shfl_xor_sync(0xffffffffu, p, 1);
        if (s == 0) {
            float zv = z_p[(size_t)l * (2*D_INNER)];
            y_p[(size_t)l * D_INNER] = (p + xv * Dv) * siluf(zv);
        }
    }
}

// ---------------- launcher --------------------------------------------------
extern "C" void kernel_launch(void* const* d_in, const int* in_sizes, int n_in,
                              void* d_out, int out_size) {
    const float* x      = (const float*)d_in[0];
    const float* in_w   = (const float*)d_in[1];
    const float* conv_w = (const float*)d_in[2];
    const float* conv_b = (const float*)d_in[3];
    const float* xp_w   = (const float*)d_in[4];
    const float* dt_w   = (const float*)d_in[5];
    const float* dt_b   = (const float*)d_in[6];
    const float* A_log  = (const float*)d_in[7];
    const float* Dskip  = (const float*)d_in[8];
    const float* out_w  = (const float*)d_in[9];
    const float* ln_g   = (const float*)d_in[10];
    const float* ln_b   = (const float*)d_in[11];

    float *gx, *gln, *gxz, *gxm, *gxdbl, *gdt, *gy, *gsA, *gsB;
    __nv_bfloat16 *ga3, *gb3;
    cudaGetSymbolAddress((void**)&gx,    g_x);
    cudaGetSymbolAddress((void**)&gln,   g_ln);
    cudaGetSymbolAddress((void**)&gxz,   g_xz);
    cudaGetSymbolAddress((void**)&gxm,   g_xm);
    cudaGetSymbolAddress((void**)&gxdbl, g_xdbl);
    cudaGetSymbolAddress((void**)&gdt,   g_dt);
    cudaGetSymbolAddress((void**)&gy,    g_y);
    cudaGetSymbolAddress((void**)&gsA,   g_sA);
    cudaGetSymbolAddress((void**)&gsB,   g_sB);
    cudaGetSymbolAddress((void**)&ga3,   g_a3);
    cudaGetSymbolAddress((void**)&gb3,   g_b3);

    cudaFuncSetAttribute(mma_gemm<0>, cudaFuncAttributeMaxDynamicSharedMemorySize, SMEM_DYN);
    cudaFuncSetAttribute(mma_gemm<1>, cudaFuncAttributeMaxDynamicSharedMemorySize, SMEM_DYN);
    cudaFuncSetAttribute(mma_gemm<2>, cudaFuncAttributeMaxDynamicSharedMemorySize, SMEM_DYN);

    {   // residual stream init
        int n4 = NROWS * D_MODEL / 4;
        copy4_kernel<<<(n4 + 255) / 256, 256>>>(x, gx, n4);
    }

    for (int i = 0; i < N_LAYERS; i++) {
        const float* inw_i = in_w  + (size_t)i * (2*D_INNER) * D_MODEL;
        const float* cw_i  = conv_w + (size_t)i * D_INNER * D_CONV;
        const float* cb_i  = conv_b + (size_t)i * D_INNER;
        const float* xpw_i = xp_w  + (size_t)i * XDBL_W * D_INNER;
        const float* dtw_i = dt_w  + (size_t)i * D_INNER * DT_RANK;
        const float* dtb_i = dt_b  + (size_t)i * D_INNER;
        const float* Al_i  = A_log + (size_t)i * D_INNER * D_STATE;
        const float* Ds_i  = Dskip + (size_t)i * D_INNER;
        const float* ow_i  = out_w + (size_t)i * D_MODEL * D_INNER;

        // 1. layernorm
        layernorm_kernel<<<NROWS, 256>>>(gx, gln, ln_g, ln_b);

        // 2. in_proj: xz[2048,4096] = ln @ in_w^T   (K3=3072)
        {
            int ab = (NROWS * D_MODEL) / 256, wb = (2*D_INNER * D_MODEL) / 256;
            convert_pair<<<ab + wb, 256>>>(gln, D_MODEL, D_MODEL, ga3, ab,
                                           inw_i, D_MODEL, 2*D_INNER, D_MODEL, gb3);
            mma_gemm<0><<<dim3(2*D_INNER/64, NROWS/128), 256, SMEM_DYN>>>(
                ga3, gb3, gxz, 2*D_INNER, 2*D_INNER, 3*D_MODEL, nullptr);
        }

        // 3. conv + silu
        conv_silu_kernel<<<dim3(D_INNER/256, SEQ, BATCH), 256>>>(gxz, cw_i, cb_i, gxm);

        // 4. x_proj: xdbl[2048,96] = xm @ xp_w^T    (K3=6144, N pad 128)
        {
            int ab = (NROWS * D_INNER) / 256, wb = (128 * D_INNER) / 256;
            convert_pair<<<ab + wb, 256>>>(gxm, D_INNER, D_INNER, ga3, ab,
                                           xpw_i, D_INNER, XDBL_W, D_INNER, gb3);
            mma_gemm<0><<<dim3(2, NROWS/128), 256, SMEM_DYN>>>(
                ga3, gb3, gxdbl, XDBL_W, XDBL_W, 3*D_INNER, nullptr);
        }

        // 5. dt: softplus(xdbl[:,:64] @ dt_w^T + dt_b)   (K3=192)
        {
            int ab = (NROWS * DT_RANK) / 256, wb = (D_INNER * DT_RANK) / 256;
            convert_pair<<<ab + wb, 256>>>(gxdbl, XDBL_W, DT_RANK, ga3, ab,
                                           dtw_i, DT_RANK, D_INNER, DT_RANK, gb3);
            mma_gemm<1><<<dim3(D_INNER/64, NROWS/128), 256, SMEM_DYN>>>(
                ga3, gb3, gdt, D_INNER, D_INNER, 3*DT_RANK, dtb_i);
        }

        // 6. selective scan (2-pass chunked) + gating
        scan_pass1<<<(3*NCH)/256, 256>>>(gdt, gxm, gxdbl, Al_i, gsA, gsB);
        scan_pass2<<<(NCHUNK*NCH)/256, 256>>>(gdt, gxm, gxdbl, gxz, Al_i, Ds_i,
                                              gsA, gsB, gy);

        // 7. out_proj residual: x += y @ out_w^T    (K3=6144)
        {
            int ab = (NROWS * D_INNER) / 256, wb = (D_MODEL * D_INNER) / 256;
            convert_pair<<<ab + wb, 256>>>(gy, D_INNER, D_INNER, ga3, ab,
                                           ow_i, D_INNER, D_MODEL, D_INNER, gb3);
            mma_gemm<2><<<dim3(D_MODEL/64, NROWS/128), 256, SMEM_DYN>>>(
                ga3, gb3, gx, D_MODEL, D_MODEL, 3*D_INNER, nullptr);
        }
    }

    // final layernorm -> output
    layernorm_kernel<<<NROWS, 256>>>(gx, (float*)d_out, ln_g, ln_b);
}